// round 8
// baseline (speedup 1.0000x reference)
#include <cuda_runtime.h>
#include <stdint.h>

#define BB 128
#define SS 512
#define HH 100
#define EE 300
#define CC 20

typedef unsigned long long ull;

// Scratch (device globals: allocation-free per harness rules)
__device__ float d_X [SS*BB*EE];          // dropout(embedding), [s,b,e]
__device__ float d_GI[SS*BB*EE];          // x @ w_ih^T + b_ih,  [s,b,3H]
__device__ unsigned char d_m2[SS*BB*HH];  // dropout2 keep mask

// ---------------------------------------------------------------------------
// f32x2 packed-math helpers (Blackwell FFMA2) — IEEE-identical rounding to FFMA
// ---------------------------------------------------------------------------
__device__ __forceinline__ ull fma2(ull a, ull b, ull c) {
    ull d;
    asm("fma.rn.f32x2 %0, %1, %2, %3;" : "=l"(d) : "l"(a), "l"(b), "l"(c));
    return d;
}
__device__ __forceinline__ ull pack2(float lo, float hi) {
    ull r; asm("mov.b64 %0, {%1,%2};" : "=l"(r) : "f"(lo), "f"(hi)); return r;
}
__device__ __forceinline__ float2 unpack2(ull v) {
    float lo, hi; asm("mov.b64 {%0,%1}, %2;" : "=f"(lo), "=f"(hi) : "l"(v));
    return make_float2(lo, hi);
}

// ---------------------------------------------------------------------------
// JAX threefry2x32 (partitionable counter mode): bits(i) = o0 ^ o1 of
// E_{(k0,k1)}(x0=0, x1=i).  keep (bernoulli p=0.5) iff bits < 2^31.
// ---------------------------------------------------------------------------
__device__ __forceinline__ unsigned int tf_bits(unsigned int k0, unsigned int k1,
                                                unsigned int idx)
{
    unsigned int ks2 = k0 ^ k1 ^ 0x1BD11BDAu;
    unsigned int x0 = k0;
    unsigned int x1 = idx + k1;
#define TFR(r) { x0 += x1; x1 = __funnelshift_l(x1, x1, (r)); x1 ^= x0; }
    TFR(13) TFR(15) TFR(26) TFR(6)
    x0 += k1;  x1 += ks2 + 1u;
    TFR(17) TFR(29) TFR(16) TFR(24)
    x0 += ks2; x1 += k0 + 2u;
    TFR(13) TFR(15) TFR(26) TFR(6)
    x0 += k0;  x1 += k1 + 3u;
    TFR(17) TFR(29) TFR(16) TFR(24)
    x0 += k1;  x1 += ks2 + 4u;
    TFR(13) TFR(15) TFR(26) TFR(6)
    x0 += ks2; x1 += k0 + 5u;
#undef TFR
    return x0 ^ x1;
}

// ---------------------------------------------------------------------------
// K1: X[s,b,:] = where(m1, emb[tok[b,s]] * 2, 0)
// ---------------------------------------------------------------------------
__global__ void k_embed(const int* __restrict__ inputs, const float* __restrict__ emb,
                        unsigned int k0, unsigned int k1)
{
    int row = blockIdx.x;               // row = s*128 + b
    int t   = threadIdx.x;
    if (t >= EE) return;
    int s = row >> 7;
    int b = row & 127;
    int tok = inputs[b*SS + s];
    unsigned int idx  = (unsigned int)((b*SS + s)*EE + t);   // (B,S,E) flat
    unsigned int bits = tf_bits(k0, k1, idx);
    float v = ((int)bits >= 0) ? 2.0f * emb[tok*EE + t] : 0.0f;
    d_X[row*EE + t] = v;
}

// ---------------------------------------------------------------------------
// K2: m2 keep mask over (S,B,H) flat
// ---------------------------------------------------------------------------
__global__ void k_m2(unsigned int k0, unsigned int k1)
{
    unsigned int idx = blockIdx.x * 256u + threadIdx.x;
    if (idx < (unsigned int)(SS*BB*HH))
        d_m2[idx] = (unsigned char)(((int)tf_bits(k0, k1, idx) >= 0) ? 1 : 0);
}

// ---------------------------------------------------------------------------
// K3: GI = X @ w_ih^T + b_ih     M=65536, N=300, K=300
// BM=128, BN=100, BK=15; 320 threads; 8x5 register tile as 4 row-pair
// f32x2 accumulators x 5 cols (summation order identical to serial FFMA).
// ---------------------------------------------------------------------------
__global__ __launch_bounds__(320, 2)
void k_gemm(const float* __restrict__ w_ih, const float* __restrict__ b_ih)
{
    __shared__ __align__(16) float Xs[15*132];   // [kk][m], padded stride 132
    __shared__ float Ws[15*102];                 // [kk][j], padded stride 102
    int j0   = blockIdx.x * 100;
    int row0 = blockIdx.y * 128;
    int tid = threadIdx.x;
    int tx = tid % 20;
    int ty = tid / 20;

    ull acc[4][5];
#pragma unroll
    for (int i = 0; i < 4; i++)
#pragma unroll
        for (int j = 0; j < 5; j++) acc[i][j] = 0ull;

    for (int k0 = 0; k0 < 300; k0 += 15) {
#pragma unroll
        for (int it = 0; it < 6; it++) {
            int l = tid + it*320;
            int m = l / 15, kk = l - m*15;
            Xs[kk*132 + m] = d_X[(row0 + m)*300 + k0 + kk];
        }
#pragma unroll
        for (int it = 0; it < 5; it++) {
            int l = tid + it*320;
            if (l < 1500) {
                int j = l / 15, kk = l - j*15;
                Ws[kk*102 + j] = w_ih[(j0 + j)*300 + k0 + kk];
            }
        }
        __syncthreads();
#pragma unroll
        for (int kk = 0; kk < 15; kk++) {
            const ull* xp = reinterpret_cast<const ull*>(&Xs[kk*132 + ty*8]);
            ull av[4];
#pragma unroll
            for (int i = 0; i < 4; i++) av[i] = xp[i];
            ull bv[5];
#pragma unroll
            for (int j = 0; j < 5; j++) {
                float b = Ws[kk*102 + tx*5 + j];
                bv[j] = pack2(b, b);
            }
#pragma unroll
            for (int i = 0; i < 4; i++)
#pragma unroll
                for (int j = 0; j < 5; j++)
                    acc[i][j] = fma2(av[i], bv[j], acc[i][j]);
        }
        __syncthreads();
    }
#pragma unroll
    for (int j = 0; j < 5; j++) {
        float bias = b_ih[j0 + tx*5 + j];
#pragma unroll
        for (int i = 0; i < 4; i++) {
            float2 v = unpack2(acc[i][j]);
            d_GI[(row0 + ty*8 + 2*i    )*300 + j0 + tx*5 + j] = v.x + bias;
            d_GI[(row0 + ty*8 + 2*i + 1)*300 + j0 + tx*5 + j] = v.y + bias;
        }
    }
}

// accurate sigmoid (libm expf — numerics proven at 6.3e-8)
__device__ __forceinline__ float sigmoidf_acc(float x) {
    return 1.0f / (1.0f + expf(-x));
}

// ---------------------------------------------------------------------------
// K4: per-batch GRU recurrence + dropout2 + linear + log_softmax.
// 128 CTAs (one per b), 640 threads (20 warps):
//   warps 0..18 (608 threads = exactly 19 warps): k-split-2 gh dots.
//     thread t -> row = t>>1 (0..303, clamped to 299; rows>=300 discarded),
//     half = t&1 owns 25 of the 50 ull (f32 pair) weight chunks; halves are
//     combined with one shfl_xor(1).  t<200-row results fold sigmoid inline.
//   warp 19, lanes 0..19: logits + log_softmax of step s-1 (w_lin in smem),
//     fully overlapped (proven hidden by R6/R7 A/B).
//   phase2: t<100 gate update (tanhf) + dropout2 into double-buffered hd_s.
// ---------------------------------------------------------------------------
__global__ __launch_bounds__(640, 1)
void k_recur(const float* __restrict__ w_hh, const float* __restrict__ b_hh,
             const float* __restrict__ w_lin, const float* __restrict__ b_lin,
             float* __restrict__ out)
{
    __shared__ __align__(16) float h_s[HH];
    __shared__ __align__(16) float hd_s[2][HH];
    __shared__ float rz_s[2*HH];     // [0,100)=r, [100,200)=z
    __shared__ float ghn_s[HH];      // gh of n rows
    __shared__ float gin_s[HH];      // gi of n rows
    __shared__ __align__(16) float wl_s[CC*HH];   // w_lin rows (logits warp)
    __shared__ float bl_s[CC];

    int b = blockIdx.x;
    int t = threadIdx.x;
    int warp = t >> 5, lane = t & 31;
    const bool is_dotw = (warp < 19);          // 608 threads, full warps
    int rowu = t >> 1;                         // 0..303 for dot threads
    int row  = (rowu < 300) ? rowu : 299;      // clamp for safe loads
    int half = t & 1;

    // stage w_lin / b_lin into smem (logits warp reads them there)
    for (int i = t; i < CC*HH; i += 640) wl_s[i] = w_lin[i];
    if (t < CC) bl_s[t] = b_lin[t];

    ull w2[25];                      // this half's 25 weight pairs
    float bias2 = 0.f;
    if (is_dotw) {
        const ull* wp = reinterpret_cast<const ull*>(w_hh + row*HH);
#pragma unroll
        for (int k = 0; k < 25; k++) w2[k] = wp[half*25 + k];
        if (half == 0) bias2 = b_hh[row];
    }

    if (t < HH) h_s[t] = 0.f;
    __syncthreads();

    float gi_cur = (is_dotw && half == 0) ? d_GI[b*300 + row] : 0.f;
    unsigned char m_cur = (t < HH) ? d_m2[b*HH + t] : (unsigned char)0;

    for (int s = 0; s < SS; s++) {
        // prefetch next step's gi row + mask (in flight under the dot)
        float gi_next = 0.f; unsigned char m_next = 0;
        if (s + 1 < SS) {
            if (is_dotw && half == 0)
                gi_next = __ldg(&d_GI[((s+1)*BB + b)*300 + row]);
            if (t < HH)
                m_next = __ldg(&d_m2[((s+1)*BB + b)*HH + t]);
        }

        if (is_dotw) {
            const ulonglong2* hp2 = reinterpret_cast<const ulonglong2*>(h_s);
            const ull*        hp1 = reinterpret_cast<const ull*>(h_s);
            ull a0 = (half == 0) ? pack2(bias2, 0.f) : 0ull;
            ull a1 = 0ull, a2 = 0ull, a3 = 0ull;
            if (half == 0) {                     // ull chunks 0..24
#pragma unroll
                for (int j = 0; j < 12; j += 2) {
                    ulonglong2 hA = hp2[j], hB = hp2[j+1];
                    a0 = fma2(w2[2*j    ], hA.x, a0);
                    a1 = fma2(w2[2*j + 1], hA.y, a1);
                    a2 = fma2(w2[2*j + 2], hB.x, a2);
                    a3 = fma2(w2[2*j + 3], hB.y, a3);
                }
                a0 = fma2(w2[24], hp1[24], a0);
            } else {                             // ull chunks 25..49
                a0 = fma2(w2[0], hp1[25], a0);
#pragma unroll
                for (int j = 0; j < 12; j += 2) {
                    ulonglong2 hA = hp2[13+j], hB = hp2[14+j];
                    a0 = fma2(w2[1 + 2*j], hA.x, a0);
                    a1 = fma2(w2[2 + 2*j], hA.y, a1);
                    a2 = fma2(w2[3 + 2*j], hB.x, a2);
                    a3 = fma2(w2[4 + 2*j], hB.y, a3);
                }
            }
            float2 f0 = unpack2(a0), f1 = unpack2(a1);
            float2 f2 = unpack2(a2), f3 = unpack2(a3);
            float part = ((f0.x + f0.y) + (f1.x + f1.y)) +
                         ((f2.x + f2.y) + (f3.x + f3.y));
            float gh = part + __shfl_xor_sync(0xffffffffu, part, 1);
            if (half == 0 && rowu < 300) {
                if (rowu < 2*HH) {
                    rz_s[rowu] = sigmoidf_acc(gi_cur + gh);  // folded sigmoid
                } else {
                    ghn_s[rowu - 2*HH] = gh;
                    gin_s[rowu - 2*HH] = gi_cur;
                }
            }
        } else if (s > 0) {
            // warp 19: logits + log_softmax for step s-1 (fully overlapped)
            int sp = s - 1;
            int buf = sp & 1;
            float logit = __int_as_float(0xff800000);
            if (lane < CC) {
                const ulonglong2* hp = reinterpret_cast<const ulonglong2*>(hd_s[buf]);
                const ull* wp = reinterpret_cast<const ull*>(wl_s + lane*HH);
                ull a0 = pack2(bl_s[lane], 0.f), a1 = 0ull;
#pragma unroll
                for (int k = 0; k < 25; k++) {
                    ulonglong2 hv = hp[k];
                    a0 = fma2(wp[2*k    ], hv.x, a0);
                    a1 = fma2(wp[2*k + 1], hv.y, a1);
                }
                float2 f0 = unpack2(a0), f1 = unpack2(a1);
                logit = (f0.x + f0.y) + (f1.x + f1.y);
            }
            float mx = logit;
#pragma unroll
            for (int o = 16; o > 0; o >>= 1)
                mx = fmaxf(mx, __shfl_xor_sync(0xffffffffu, mx, o));
            float ex = (lane < CC) ? expf(logit - mx) : 0.f;
            float sm = ex;
#pragma unroll
            for (int o = 16; o > 0; o >>= 1)
                sm += __shfl_xor_sync(0xffffffffu, sm, o);
            if (lane < CC)
                out[(b*CC + lane)*SS + sp] = logit - mx - logf(sm);
        }
        __syncthreads();

        if (t < HH) {
            float r = rz_s[t];
            float z = rz_s[HH + t];
            float n = tanhf(gin_s[t] + r * ghn_s[t]);
            float hn = (1.f - z) * n + z * h_s[t];
            h_s[t] = hn;
            hd_s[s & 1][t] = m_cur ? 2.f * hn : 0.f;
        }
        __syncthreads();
        gi_cur = gi_next; m_cur = m_next;
    }

    // tail: logits for the last step (s = 511)
    if (warp == 19) {
        int sp = SS - 1;
        int buf = sp & 1;
        float logit = __int_as_float(0xff800000);
        if (lane < CC) {
            const ulonglong2* hp = reinterpret_cast<const ulonglong2*>(hd_s[buf]);
            const ull* wp = reinterpret_cast<const ull*>(wl_s + lane*HH);
            ull a0 = pack2(bl_s[lane], 0.f), a1 = 0ull;
#pragma unroll
            for (int k = 0; k < 25; k++) {
                ulonglong2 hv = hp[k];
                a0 = fma2(wp[2*k    ], hv.x, a0);
                a1 = fma2(wp[2*k + 1], hv.y, a1);
            }
            float2 f0 = unpack2(a0), f1 = unpack2(a1);
            logit = (f0.x + f0.y) + (f1.x + f1.y);
        }
        float mx = logit;
#pragma unroll
        for (int o = 16; o > 0; o >>= 1)
            mx = fmaxf(mx, __shfl_xor_sync(0xffffffffu, mx, o));
        float ex = (lane < CC) ? expf(logit - mx) : 0.f;
        float sm = ex;
#pragma unroll
        for (int o = 16; o > 0; o >>= 1)
            sm += __shfl_xor_sync(0xffffffffu, sm, o);
        if (lane < CC)
            out[(b*CC + lane)*SS + sp] = logit - mx - logf(sm);
    }
}

// ---------------------------------------------------------------------------
// host-side threefry for key derivation
// ---------------------------------------------------------------------------
static void tf_host(unsigned int k0, unsigned int k1, unsigned int x0i, unsigned int x1i,
                    unsigned int* o0, unsigned int* o1)
{
    unsigned int ks[3] = { k0, k1, k0 ^ k1 ^ 0x1BD11BDAu };
    const int rotA[4] = {13, 15, 26, 6}, rotB[4] = {17, 29, 16, 24};
    unsigned int x0 = x0i + ks[0], x1 = x1i + ks[1];
    for (int i = 0; i < 5; i++) {
        const int* r = (i & 1) ? rotB : rotA;
        for (int j = 0; j < 4; j++) {
            x0 += x1;
            x1 = (x1 << r[j]) | (x1 >> (32 - r[j]));
            x1 ^= x0;
        }
        x0 += ks[(i + 1) % 3];
        x1 += ks[(i + 2) % 3] + (unsigned int)(i + 1);
    }
    *o0 = x0; *o1 = x1;
}

extern "C" void kernel_launch(void* const* d_in, const int* in_sizes, int n_in,
                              void* d_out, int out_size)
{
    const int*   inputs = (const int*)  d_in[0];
    const float* emb    = (const float*)d_in[1];
    const float* w_ih   = (const float*)d_in[2];
    const float* w_hh   = (const float*)d_in[3];
    const float* b_ih   = (const float*)d_in[4];
    const float* b_hh   = (const float*)d_in[5];
    const float* w_lin  = (const float*)d_in[6];
    const float* b_lin  = (const float*)d_in[7];
    float* out = (float*)d_out;
    (void)in_sizes; (void)n_in; (void)out_size;

    unsigned int dk1_0, dk1_1, dk2_0, dk2_1;
    tf_host(0u, 42u, 0u, 0u, &dk1_0, &dk1_1);
    tf_host(0u, 42u, 0u, 1u, &dk2_0, &dk2_1);

    k_embed<<<SS*BB, 320>>>(inputs, emb, dk1_0, dk1_1);
    k_m2<<<(SS*BB*HH + 255)/256, 256>>>(dk2_0, dk2_1);
    k_gemm<<<dim3(3, 512), 320>>>(w_ih, b_ih);
    k_recur<<<BB, 640>>>(w_hh, b_hh, w_lin, b_lin, out);
}

// round 9
// speedup vs baseline: 1.2754x; 1.2754x over previous
#include <cuda_runtime.h>
#include <stdint.h>

#define BB 128
#define SS 512
#define HH 100
#define EE 300
#define CC 20

typedef unsigned long long ull;

// Scratch (device globals: allocation-free per harness rules)
__device__ float d_X [SS*BB*EE];          // dropout(embedding), [s,b,e]
__device__ float d_GI[SS*BB*EE];          // x @ w_ih^T + b_ih,  [s,b,3H]
__device__ unsigned char d_m2[SS*BB*HH];  // dropout2 keep mask

// ---------------------------------------------------------------------------
// f32x2 packed-math helpers (Blackwell FFMA2) — IEEE-identical rounding to FFMA
// ---------------------------------------------------------------------------
__device__ __forceinline__ ull fma2(ull a, ull b, ull c) {
    ull d;
    asm("fma.rn.f32x2 %0, %1, %2, %3;" : "=l"(d) : "l"(a), "l"(b), "l"(c));
    return d;
}
__device__ __forceinline__ ull pack2(float lo, float hi) {
    ull r; asm("mov.b64 %0, {%1,%2};" : "=l"(r) : "f"(lo), "f"(hi)); return r;
}
__device__ __forceinline__ float2 unpack2(ull v) {
    float lo, hi; asm("mov.b64 {%0,%1}, %2;" : "=f"(lo), "=f"(hi) : "l"(v));
    return make_float2(lo, hi);
}

// ---------------------------------------------------------------------------
// JAX threefry2x32 (partitionable counter mode): bits(i) = o0 ^ o1 of
// E_{(k0,k1)}(x0=0, x1=i).  keep (bernoulli p=0.5) iff bits < 2^31.
// ---------------------------------------------------------------------------
__device__ __forceinline__ unsigned int tf_bits(unsigned int k0, unsigned int k1,
                                                unsigned int idx)
{
    unsigned int ks2 = k0 ^ k1 ^ 0x1BD11BDAu;
    unsigned int x0 = k0;
    unsigned int x1 = idx + k1;
#define TFR(r) { x0 += x1; x1 = __funnelshift_l(x1, x1, (r)); x1 ^= x0; }
    TFR(13) TFR(15) TFR(26) TFR(6)
    x0 += k1;  x1 += ks2 + 1u;
    TFR(17) TFR(29) TFR(16) TFR(24)
    x0 += ks2; x1 += k0 + 2u;
    TFR(13) TFR(15) TFR(26) TFR(6)
    x0 += k0;  x1 += k1 + 3u;
    TFR(17) TFR(29) TFR(16) TFR(24)
    x0 += k1;  x1 += ks2 + 4u;
    TFR(13) TFR(15) TFR(26) TFR(6)
    x0 += ks2; x1 += k0 + 5u;
#undef TFR
    return x0 ^ x1;
}

// ---------------------------------------------------------------------------
// K1: X[s,b,:] = where(m1, emb[tok[b,s]] * 2, 0)
// ---------------------------------------------------------------------------
__global__ void k_embed(const int* __restrict__ inputs, const float* __restrict__ emb,
                        unsigned int k0, unsigned int k1)
{
    int row = blockIdx.x;               // row = s*128 + b
    int t   = threadIdx.x;
    if (t >= EE) return;
    int s = row >> 7;
    int b = row & 127;
    int tok = inputs[b*SS + s];
    unsigned int idx  = (unsigned int)((b*SS + s)*EE + t);   // (B,S,E) flat
    unsigned int bits = tf_bits(k0, k1, idx);
    float v = ((int)bits >= 0) ? 2.0f * emb[tok*EE + t] : 0.0f;
    d_X[row*EE + t] = v;
}

// ---------------------------------------------------------------------------
// K2: m2 keep mask over (S,B,H) flat
// ---------------------------------------------------------------------------
__global__ void k_m2(unsigned int k0, unsigned int k1)
{
    unsigned int idx = blockIdx.x * 256u + threadIdx.x;
    if (idx < (unsigned int)(SS*BB*HH))
        d_m2[idx] = (unsigned char)(((int)tf_bits(k0, k1, idx) >= 0) ? 1 : 0);
}

// ---------------------------------------------------------------------------
// K3: GI = X @ w_ih^T + b_ih     M=65536, N=300, K=300
// BM=128, BN=100, BK=15; 320 threads; 8x5 register tile as 4 row-pair
// f32x2 accumulators x 5 cols (summation order identical to serial FFMA).
// ---------------------------------------------------------------------------
__global__ __launch_bounds__(320, 2)
void k_gemm(const float* __restrict__ w_ih, const float* __restrict__ b_ih)
{
    __shared__ __align__(16) float Xs[15*132];   // [kk][m], padded stride 132
    __shared__ float Ws[15*102];                 // [kk][j], padded stride 102
    int j0   = blockIdx.x * 100;
    int row0 = blockIdx.y * 128;
    int tid = threadIdx.x;
    int tx = tid % 20;
    int ty = tid / 20;

    ull acc[4][5];
#pragma unroll
    for (int i = 0; i < 4; i++)
#pragma unroll
        for (int j = 0; j < 5; j++) acc[i][j] = 0ull;

    for (int k0 = 0; k0 < 300; k0 += 15) {
#pragma unroll
        for (int it = 0; it < 6; it++) {
            int l = tid + it*320;
            int m = l / 15, kk = l - m*15;
            Xs[kk*132 + m] = d_X[(row0 + m)*300 + k0 + kk];
        }
#pragma unroll
        for (int it = 0; it < 5; it++) {
            int l = tid + it*320;
            if (l < 1500) {
                int j = l / 15, kk = l - j*15;
                Ws[kk*102 + j] = w_ih[(j0 + j)*300 + k0 + kk];
            }
        }
        __syncthreads();
#pragma unroll
        for (int kk = 0; kk < 15; kk++) {
            const ull* xp = reinterpret_cast<const ull*>(&Xs[kk*132 + ty*8]);
            ull av[4];
#pragma unroll
            for (int i = 0; i < 4; i++) av[i] = xp[i];
            ull bv[5];
#pragma unroll
            for (int j = 0; j < 5; j++) {
                float b = Ws[kk*102 + tx*5 + j];
                bv[j] = pack2(b, b);
            }
#pragma unroll
            for (int i = 0; i < 4; i++)
#pragma unroll
                for (int j = 0; j < 5; j++)
                    acc[i][j] = fma2(av[i], bv[j], acc[i][j]);
        }
        __syncthreads();
    }
#pragma unroll
    for (int j = 0; j < 5; j++) {
        float bias = b_ih[j0 + tx*5 + j];
#pragma unroll
        for (int i = 0; i < 4; i++) {
            float2 v = unpack2(acc[i][j]);
            d_GI[(row0 + ty*8 + 2*i    )*300 + j0 + tx*5 + j] = v.x + bias;
            d_GI[(row0 + ty*8 + 2*i + 1)*300 + j0 + tx*5 + j] = v.y + bias;
        }
    }
}

// accurate sigmoid (libm expf — numerics proven at 6.3e-8)
__device__ __forceinline__ float sigmoidf_acc(float x) {
    return 1.0f / (1.0f + expf(-x));
}

// ---------------------------------------------------------------------------
// K4: per-batch GRU recurrence + dropout2 + linear + log_softmax.
// ONE __syncthreads per step.  128 CTAs (one per b), 352 threads (11 warps):
//   warps 0..9, lanes 0..29: unit u = w*10 + l/3, gate g = l%3,
//     w_hh row g*100+u register-resident; dot over double-buffered h_s[p];
//     r,z sigmoids in-lane; shfl r,z to the n-lane (g==2) which does
//     tanh + blend and stores h_s[1-p][u] + hd_s[p][u].
//   warp 10, lanes 0..19: logits + log_softmax of step s-1 from hd_s[1-p]
//     (proven fully overlapped by the R6/R7 A/B).
// ---------------------------------------------------------------------------
__global__ __launch_bounds__(352, 1)
void k_recur(const float* __restrict__ w_hh, const float* __restrict__ b_hh,
             const float* __restrict__ w_lin, const float* __restrict__ b_lin,
             float* __restrict__ out)
{
    __shared__ __align__(16) float h_s[2][HH + 4];    // double-buffered h
    __shared__ __align__(16) float hd_s[2][HH];       // double-buffered dropout(h)
    __shared__ __align__(16) float wl_s[CC*HH];       // w_lin rows (logits warp)
    __shared__ float bl_s[CC];

    int b = blockIdx.x;
    int t = threadIdx.x;
    int warp = t >> 5, lane = t & 31;
    const bool is_dot = (warp < 10) && (lane < 30);
    const unsigned DOTMASK = 0x3fffffffu;             // lanes 0..29

    int u = warp*10 + lane/3;         // hidden unit 0..99
    int g = lane - 3*(lane/3);        // 0:r 1:z 2:n
    int row = g*HH + u;               // w_hh/gi row 0..299

    // stage w_lin / b_lin into smem
    for (int i = t; i < CC*HH; i += 352) wl_s[i] = w_lin[i];
    if (t < CC) bl_s[t] = b_lin[t];

    ull w2[50];                       // packed w_hh row (dot lanes only)
    float bias2 = 0.f;
    if (is_dot) {
        const ull* wp = reinterpret_cast<const ull*>(w_hh + row*HH);
#pragma unroll
        for (int k = 0; k < 50; k++) w2[k] = wp[k];
        bias2 = b_hh[row];
    }

    if (t < HH) { h_s[0][t] = 0.f; h_s[1][t] = 0.f; }
    __syncthreads();

    float gi_cur = is_dot ? d_GI[b*300 + row] : 0.f;
    unsigned char m_cur = (is_dot && g == 2) ? d_m2[b*HH + u] : (unsigned char)0;

    for (int s = 0; s < SS; s++) {
        int p = s & 1;
        // prefetch next step's gi row + mask (in flight under the dot)
        float gi_next = 0.f; unsigned char m_next = 0;
        if (s + 1 < SS) {
            if (is_dot) gi_next = __ldg(&d_GI[((s+1)*BB + b)*300 + row]);
            if (is_dot && g == 2) m_next = __ldg(&d_m2[((s+1)*BB + b)*HH + u]);
        }

        if (is_dot) {
            const ulonglong2* hp = reinterpret_cast<const ulonglong2*>(h_s[p]);
            const ull*        h1 = reinterpret_cast<const ull*>(h_s[p]);
            ull a0 = pack2(bias2, 0.f), a1 = 0ull, a2 = 0ull, a3 = 0ull;
#pragma unroll
            for (int k = 0; k < 24; k += 2) {       // 48 pairs
                ulonglong2 hA = hp[k], hB = hp[k+1];
                a0 = fma2(w2[2*k    ], hA.x, a0);
                a1 = fma2(w2[2*k + 1], hA.y, a1);
                a2 = fma2(w2[2*k + 2], hB.x, a2);
                a3 = fma2(w2[2*k + 3], hB.y, a3);
            }
            {                                        // last 2 pairs (48,49)
                a0 = fma2(w2[48], h1[48], a0);
                a1 = fma2(w2[49], h1[49], a1);
            }
            float2 f0 = unpack2(a0), f1 = unpack2(a1);
            float2 f2 = unpack2(a2), f3 = unpack2(a3);
            float gh = ((f0.x + f0.y) + (f1.x + f1.y)) +
                       ((f2.x + f2.y) + (f3.x + f3.y));

            // r/z lanes: sigmoid in-lane.  n lane: keep gh_n, gi_n separate.
            float act = (g < 2) ? sigmoidf_acc(gi_cur + gh) : 0.f;
            int base = lane - g;                     // lane of g==0 for this unit
            float r_v = __shfl_sync(DOTMASK, act, base);
            float z_v = __shfl_sync(DOTMASK, act, base + 1);
            if (g == 2) {
                float n  = tanhf(gi_cur + r_v * gh);
                float hp_ = h_s[p][u];
                float hn = (1.f - z_v) * n + z_v * hp_;
                h_s[1 - p][u] = hn;
                hd_s[p][u]    = m_cur ? 2.f * hn : 0.f;
            }
        } else if (warp == 10 && s > 0) {
            // logits + log_softmax for step s-1 (fully overlapped)
            int sp = s - 1;
            float logit = __int_as_float(0xff800000);
            if (lane < CC) {
                const ulonglong2* hq = reinterpret_cast<const ulonglong2*>(hd_s[1 - p]);
                const ull* wp = reinterpret_cast<const ull*>(wl_s + lane*HH);
                ull a0 = pack2(bl_s[lane], 0.f), a1 = 0ull;
#pragma unroll
                for (int k = 0; k < 25; k++) {
                    ulonglong2 hv = hq[k];
                    a0 = fma2(wp[2*k    ], hv.x, a0);
                    a1 = fma2(wp[2*k + 1], hv.y, a1);
                }
                float2 f0 = unpack2(a0), f1 = unpack2(a1);
                logit = (f0.x + f0.y) + (f1.x + f1.y);
            }
            float mx = logit;
#pragma unroll
            for (int o = 16; o > 0; o >>= 1)
                mx = fmaxf(mx, __shfl_xor_sync(0xffffffffu, mx, o));
            float ex = (lane < CC) ? expf(logit - mx) : 0.f;
            float sm = ex;
#pragma unroll
            for (int o = 16; o > 0; o >>= 1)
                sm += __shfl_xor_sync(0xffffffffu, sm, o);
            if (lane < CC)
                out[(b*CC + lane)*SS + sp] = logit - mx - logf(sm);
        }
        __syncthreads();                             // the ONLY barrier per step
        gi_cur = gi_next; m_cur = m_next;
    }

    // tail: logits for the last step (s = 511, hd in buffer 511&1 = 1)
    if (warp == 10) {
        int sp = SS - 1;
        float logit = __int_as_float(0xff800000);
        if (lane < CC) {
            const ulonglong2* hq = reinterpret_cast<const ulonglong2*>(hd_s[1]);
            const ull* wp = reinterpret_cast<const ull*>(wl_s + lane*HH);
            ull a0 = pack2(bl_s[lane], 0.f), a1 = 0ull;
#pragma unroll
            for (int k = 0; k < 25; k++) {
                ulonglong2 hv = hq[k];
                a0 = fma2(wp[2*k    ], hv.x, a0);
                a1 = fma2(wp[2*k + 1], hv.y, a1);
            }
            float2 f0 = unpack2(a0), f1 = unpack2(a1);
            logit = (f0.x + f0.y) + (f1.x + f1.y);
        }
        float mx = logit;
#pragma unroll
        for (int o = 16; o > 0; o >>= 1)
            mx = fmaxf(mx, __shfl_xor_sync(0xffffffffu, mx, o));
        float ex = (lane < CC) ? expf(logit - mx) : 0.f;
        float sm = ex;
#pragma unroll
        for (int o = 16; o > 0; o >>= 1)
            sm += __shfl_xor_sync(0xffffffffu, sm, o);
        if (lane < CC)
            out[(b*CC + lane)*SS + sp] = logit - mx - logf(sm);
    }
}

// ---------------------------------------------------------------------------
// host-side threefry for key derivation
// ---------------------------------------------------------------------------
static void tf_host(unsigned int k0, unsigned int k1, unsigned int x0i, unsigned int x1i,
                    unsigned int* o0, unsigned int* o1)
{
    unsigned int ks[3] = { k0, k1, k0 ^ k1 ^ 0x1BD11BDAu };
    const int rotA[4] = {13, 15, 26, 6}, rotB[4] = {17, 29, 16, 24};
    unsigned int x0 = x0i + ks[0], x1 = x1i + ks[1];
    for (int i = 0; i < 5; i++) {
        const int* r = (i & 1) ? rotB : rotA;
        for (int j = 0; j < 4; j++) {
            x0 += x1;
            x1 = (x1 << r[j]) | (x1 >> (32 - r[j]));
            x1 ^= x0;
        }
        x0 += ks[(i + 1) % 3];
        x1 += ks[(i + 2) % 3] + (unsigned int)(i + 1);
    }
    *o0 = x0; *o1 = x1;
}

extern "C" void kernel_launch(void* const* d_in, const int* in_sizes, int n_in,
                              void* d_out, int out_size)
{
    const int*   inputs = (const int*)  d_in[0];
    const float* emb    = (const float*)d_in[1];
    const float* w_ih   = (const float*)d_in[2];
    const float* w_hh   = (const float*)d_in[3];
    const float* b_ih   = (const float*)d_in[4];
    const float* b_hh   = (const float*)d_in[5];
    const float* w_lin  = (const float*)d_in[6];
    const float* b_lin  = (const float*)d_in[7];
    float* out = (float*)d_out;
    (void)in_sizes; (void)n_in; (void)out_size;

    unsigned int dk1_0, dk1_1, dk2_0, dk2_1;
    tf_host(0u, 42u, 0u, 0u, &dk1_0, &dk1_1);
    tf_host(0u, 42u, 0u, 1u, &dk2_0, &dk2_1);

    k_embed<<<SS*BB, 320>>>(inputs, emb, dk1_0, dk1_1);
    k_m2<<<(SS*BB*HH + 255)/256, 256>>>(dk2_0, dk2_1);
    k_gemm<<<dim3(3, 512), 320>>>(w_ih, b_ih);
    k_recur<<<BB, 352>>>(w_hh, b_hh, w_lin, b_lin, out);
}